// round 11
// baseline (speedup 1.0000x reference)
#include <cuda_runtime.h>
#include <cstdint>
#include <cstddef>

#define TT 2048
#define BB 64

// 512 MB scratch: precomputed input projections [2][B*T][512]
__device__ float g_zpre[(size_t)2 * BB * TT * 512];

// ---------------- packed f32x2 helpers ----------------
__device__ __forceinline__ unsigned long long pk2(float lo, float hi) {
    unsigned long long r;
    asm("mov.b64 %0, {%1,%2};" : "=l"(r) : "f"(lo), "f"(hi));
    return r;
}
__device__ __forceinline__ void upk2(unsigned long long v, float& lo, float& hi) {
    asm("mov.b64 {%0,%1}, %2;" : "=f"(lo), "=f"(hi) : "l"(v));
}
__device__ __forceinline__ unsigned long long ffma2(unsigned long long a,
                                                    unsigned long long b,
                                                    unsigned long long c) {
    unsigned long long d;
    asm("fma.rn.f32x2 %0, %1, %2, %3;" : "=l"(d) : "l"(a), "l"(b), "l"(c));
    return d;
}
// branchless tanh: 1 - 2/(e^{2x}+1); exact limits, MUFU precision
__device__ __forceinline__ float tanh_f(float x) {
    float e = __expf(2.0f * x);
    return 1.0f - __fdividef(2.0f, e + 1.0f);
}

// ---------------------------------------------------------------------------
// Phase 1: Zpre = x @ W[0:128,:] + b.   (unchanged)
// ---------------------------------------------------------------------------
__global__ void __launch_bounds__(256, 1)
lstm_pre(const float* __restrict__ x,
         const float* __restrict__ W0, const float* __restrict__ bias0,
         const float* __restrict__ W1, const float* __restrict__ bias1) {
    __shared__ float xs[128 * 32];   // [row][k]
    __shared__ float ws[32 * 128];   // [k][col]

    const int dir = blockIdx.z;
    const float* W    = dir ? W1 : W0;
    const float* bias = dir ? bias1 : bias0;
    const size_t m0 = (size_t)blockIdx.y * 128;
    const int    c0 = blockIdx.x * 128;
    const int tid = threadIdx.x;
    const int tx = tid & 31;
    const int ty = tid >> 5;

    unsigned long long acc[16][2];
    #pragma unroll
    for (int i = 0; i < 16; ++i) { acc[i][0] = 0ull; acc[i][1] = 0ull; }

    for (int kc = 0; kc < 4; ++kc) {
        if (kc) __syncthreads();
        #pragma unroll
        for (int i = tid; i < 1024; i += 256) {
            int r = i >> 3, kq = i & 7;
            *(float4*)(xs + r * 32 + kq * 4) =
                *(const float4*)(x + (m0 + r) * 128 + kc * 32 + kq * 4);
        }
        #pragma unroll
        for (int i = tid; i < 1024; i += 256) {
            int k = i >> 5, c4 = (i & 31) * 4;
            *(float4*)(ws + k * 128 + c4) =
                *(const float4*)(W + (size_t)(kc * 32 + k) * 512 + c0 + c4);
        }
        __syncthreads();

        #pragma unroll
        for (int kq = 0; kq < 8; ++kq) {
            float4 av[16];
            #pragma unroll
            for (int i = 0; i < 16; ++i)
                av[i] = *(const float4*)(xs + (ty * 16 + i) * 32 + kq * 4);
            #pragma unroll
            for (int kk = 0; kk < 4; ++kk) {
                ulonglong2 bv = *(const ulonglong2*)(ws + (kq * 4 + kk) * 128 + tx * 4);
                #pragma unroll
                for (int i = 0; i < 16; ++i) {
                    float a = (kk == 0) ? av[i].x : (kk == 1) ? av[i].y
                            : (kk == 2) ? av[i].z : av[i].w;
                    unsigned long long ap = pk2(a, a);
                    acc[i][0] = ffma2(ap, bv.x, acc[i][0]);
                    acc[i][1] = ffma2(ap, bv.y, acc[i][1]);
                }
            }
        }
    }

    float bl0 = bias[c0 + tx * 4 + 0], bl1 = bias[c0 + tx * 4 + 1];
    float bl2 = bias[c0 + tx * 4 + 2], bl3 = bias[c0 + tx * 4 + 3];
    #pragma unroll
    for (int i = 0; i < 16; ++i) {
        float v0, v1, v2, v3;
        upk2(acc[i][0], v0, v1);
        upk2(acc[i][1], v2, v3);
        float4 o = make_float4(v0 + bl0, v1 + bl1, v2 + bl2, v3 + bl3);
        *(float4*)(g_zpre + ((size_t)dir * (BB * TT) + m0 + ty * 16 + i) * 512
                   + c0 + tx * 4) = o;
    }
}

// ---------------------------------------------------------------------------
// Phase 2: recurrence.
//  - lane mapping: unit ul = w*8 + (lane>>2), gate g = lane&3
//    -> the 4 gate-cols of a unit sit in adjacent lanes: shfl replaces zbuf.
//  - split arrive/wait: local-half FMA overlaps the cluster barrier wait.
//  - 2 accumulators only (register budget: w2[64]=128 regs; total must be
//    ~<=210 to avoid the R9 spill regression).
// ---------------------------------------------------------------------------
__global__ void __cluster_dims__(2, 1, 1) __launch_bounds__(256, 1)
lstm_rec(const float* __restrict__ Wfw, const float* __restrict__ Wbw,
         float* __restrict__ out) {
    __shared__ __align__(16) float hbuf[2][2][128];  // [parity][row][unit]

    uint32_t rank;
    asm("mov.u32 %0, %%cluster_ctarank;" : "=r"(rank));
    const uint32_t peer = rank ^ 1u;
    const int cid = blockIdx.x >> 1;
    const int dir = cid >> 5;
    const int b0  = (cid & 31) * 2;
    const int tid = threadIdx.x;
    const int w   = tid >> 5;
    const int l   = tid & 31;
    const int ul  = w * 8 + (l >> 2);               // unit within half 0..63
    const int g   = l & 3;                          // gate 0..3 (i,j,f,o)
    const int col = g * 128 + (int)rank * 64 + ul;  // owned z column
    const float* W = dir ? Wbw : Wfw;

    // W_h column -> registers, packed over k-pairs (rows 128..255 of W)
    unsigned long long w2[64];
    #pragma unroll
    for (int kp = 0; kp < 64; ++kp)
        w2[kp] = pk2(W[(size_t)(128 + 2 * kp) * 512 + col],
                     W[(size_t)(129 + 2 * kp) * 512 + col]);

    for (int i = tid; i < 512; i += 256) ((float*)hbuf)[i] = 0.0f;

    const uint32_t hb_l = (uint32_t)__cvta_generic_to_shared(&hbuf[0][0][0]);
    uint32_t rm_hb;
    asm("mapa.shared::cluster.u32 %0, %1, %2;" : "=r"(rm_hb) : "r"(hb_l), "r"(peer));

    // z_pre streaming pointers (rows b0, b0+1)
    const int tq0 = dir ? (TT - 1) : 0;
    const ptrdiff_t dstep = dir ? -512 : 512;
    const float* zp0 = g_zpre + ((size_t)dir * (BB * TT) + (size_t)b0 * TT + tq0) * 512 + col;
    const float* zp1 = zp0 + (size_t)TT * 512;
    float zc0 = __ldcs(zp0), zc1 = __ldcs(zp1);

    // unified gate nonlinearity: s = 1 - bet/(exp(gam*z + del) + 1)
    //   g0 (i): sigm(z)      g1 (j): tanh(z)   g2 (f): sigm(z+1)  g3 (o): sigm(z)
    const float gam = (g == 1) ? 2.0f : 1.0f;
    const float bet = (g == 1) ? 2.0f : 1.0f;
    const float del = (g == 2) ? 1.0f : 0.0f;

    float c0 = 0.0f, c1 = 0.0f;        // cell state (valid on g==0 lanes)
    const int loc_u  = (int)rank * 64;
    const int loc_kp = (int)rank * 32;
    const int rem_kp = ((int)peer) * 32;
    const int rem_u  = ((int)peer) * 64;

    __syncthreads();
    // init visible cluster-wide before any peer DSMEM stores land
    asm volatile("barrier.cluster.arrive.aligned;" ::: "memory");
    asm volatile("barrier.cluster.wait.aligned;"   ::: "memory");

    for (int t = 0; t < TT; ++t) {
        const int p  = t & 1;
        const int pn = p ^ 1;

        float zn0 = 0.0f, zn1 = 0.0f;            // prefetch next step's z
        if (t + 1 < TT) {
            zp0 += dstep; zp1 += dstep;
            zn0 = __ldcs(zp0); zn1 = __ldcs(zp1);
        }

        unsigned long long a0 = 0ull, a1 = 0ull;

        // ---- local-half FMA: our CTA's h (ordered by last __syncthreads) ----
        #pragma unroll
        for (int q = 0; q < 16; ++q) {
            ulonglong2 h0 = *(const ulonglong2*)(&hbuf[p][0][loc_u + q * 4]);
            ulonglong2 h1 = *(const ulonglong2*)(&hbuf[p][1][loc_u + q * 4]);
            a0 = ffma2(h0.x, w2[loc_kp + 2 * q],     a0);
            a0 = ffma2(h0.y, w2[loc_kp + 2 * q + 1], a0);
            a1 = ffma2(h1.x, w2[loc_kp + 2 * q],     a1);
            a1 = ffma2(h1.y, w2[loc_kp + 2 * q + 1], a1);
        }

        // ---- wait for peer's exchange of step t-1 ----
        if (t > 0)
            asm volatile("barrier.cluster.wait.aligned;" ::: "memory");

        // ---- remote-half FMA ----
        #pragma unroll
        for (int q = 0; q < 16; ++q) {
            ulonglong2 h0 = *(const ulonglong2*)(&hbuf[p][0][rem_u + q * 4]);
            ulonglong2 h1 = *(const ulonglong2*)(&hbuf[p][1][rem_u + q * 4]);
            a0 = ffma2(h0.x, w2[rem_kp + 2 * q],     a0);
            a0 = ffma2(h0.y, w2[rem_kp + 2 * q + 1], a0);
            a1 = ffma2(h1.x, w2[rem_kp + 2 * q],     a1);
            a1 = ffma2(h1.y, w2[rem_kp + 2 * q + 1], a1);
        }

        float s0l, s0h, s1l, s1h;
        upk2(a0, s0l, s0h);
        upk2(a1, s1l, s1h);
        float z0 = s0l + s0h + zc0;              // this col's z, row 0
        float z1 = s1l + s1h + zc1;              // row 1
        zc0 = zn0; zc1 = zn1;

        // per-lane gate nonlinearity (uniform code, no divergence)
        float e0 = __expf(fmaf(gam, z0, del));
        float s0 = 1.0f - __fdividef(bet, e0 + 1.0f);
        float e1 = __expf(fmaf(gam, z1, del));
        float s1 = 1.0f - __fdividef(bet, e1 + 1.0f);

        // gather the unit's 4 gate values from adjacent lanes
        const int base = l & ~3;
        float si0 = __shfl_sync(0xffffffffu, s0, base + 0);
        float sj0 = __shfl_sync(0xffffffffu, s0, base + 1);
        float sf0 = __shfl_sync(0xffffffffu, s0, base + 2);
        float so0 = __shfl_sync(0xffffffffu, s0, base + 3);
        float si1 = __shfl_sync(0xffffffffu, s1, base + 0);
        float sj1 = __shfl_sync(0xffffffffu, s1, base + 1);
        float sf1 = __shfl_sync(0xffffffffu, s1, base + 2);
        float so1 = __shfl_sync(0xffffffffu, s1, base + 3);

        if (g == 0) {                            // one lane per (unit): update c, h
            c0 = c0 * sf0 + si0 * sj0;
            c1 = c1 * sf1 + si1 * sj1;
            float h0 = so0 * tanh_f(c0);
            float h1 = so1 * tanh_f(c1);

            if (t < TT - 1) {
                hbuf[pn][0][loc_u + ul] = h0;    // local half for next step
                hbuf[pn][1][loc_u + ul] = h1;
                uint32_t off0 = (uint32_t)(((pn * 2 + 0) * 128 + loc_u + ul) * 4);
                uint32_t off1 = (uint32_t)(((pn * 2 + 1) * 128 + loc_u + ul) * 4);
                asm volatile("st.shared::cluster.f32 [%0], %1;"
                             :: "r"(rm_hb + off0), "f"(h0) : "memory");
                asm volatile("st.shared::cluster.f32 [%0], %1;"
                             :: "r"(rm_hb + off1), "f"(h1) : "memory");
            }

            const int tq = dir ? (TT - 1 - t) : t;
            out[((size_t)(b0 + 0) * TT + tq) * 256 + dir * 128 + loc_u + ul] = h0;
            out[((size_t)(b0 + 1) * TT + tq) * 256 + dir * 128 + loc_u + ul] = h1;
        }

        __syncthreads();                         // local h visible to all warps

        if (t + 1 < TT)                          // release DSMEM stores; pairs
            asm volatile("barrier.cluster.arrive.aligned;" ::: "memory");
    }
}

extern "C" void kernel_launch(void* const* d_in, const int* in_sizes, int n_in,
                              void* d_out, int out_size) {
    const float* x   = (const float*)d_in[0];
    const float* Wfw = (const float*)d_in[1];
    const float* bfw = (const float*)d_in[2];
    const float* Wbw = (const float*)d_in[3];
    const float* bbw = (const float*)d_in[4];
    float* out = (float*)d_out;

    dim3 g1(4, 1024, 2);
    lstm_pre<<<g1, 256>>>(x, Wfw, bfw, Wbw, bbw);
    lstm_rec<<<128, 256>>>(Wfw, Wbw, out);
}

// round 12
// speedup vs baseline: 1.2535x; 1.2535x over previous
#include <cuda_runtime.h>
#include <cstdint>
#include <cstddef>

#define TT 2048
#define BB 64

// 512 MB scratch: precomputed input projections [2][B*T][512]
__device__ float g_zpre[(size_t)2 * BB * TT * 512];

// ---------------- packed f32x2 helpers ----------------
__device__ __forceinline__ unsigned long long pk2(float lo, float hi) {
    unsigned long long r;
    asm("mov.b64 %0, {%1,%2};" : "=l"(r) : "f"(lo), "f"(hi));
    return r;
}
__device__ __forceinline__ void upk2(unsigned long long v, float& lo, float& hi) {
    asm("mov.b64 {%0,%1}, %2;" : "=f"(lo), "=f"(hi) : "l"(v));
}
__device__ __forceinline__ unsigned long long ffma2(unsigned long long a,
                                                    unsigned long long b,
                                                    unsigned long long c) {
    unsigned long long d;
    asm("fma.rn.f32x2 %0, %1, %2, %3;" : "=l"(d) : "l"(a), "l"(b), "l"(c));
    return d;
}
__device__ __forceinline__ float sigm(float x) {
    return __fdividef(1.0f, 1.0f + __expf(-x));
}
__device__ __forceinline__ float tanh_f(float x) {
    float e = __expf(2.0f * x);
    return 1.0f - __fdividef(2.0f, e + 1.0f);
}

// ---------------------------------------------------------------------------
// Phase 1: Zpre = x @ W[0:128,:] + b.   (unchanged — proven)
// ---------------------------------------------------------------------------
__global__ void __launch_bounds__(256, 1)
lstm_pre(const float* __restrict__ x,
         const float* __restrict__ W0, const float* __restrict__ bias0,
         const float* __restrict__ W1, const float* __restrict__ bias1) {
    __shared__ float xs[128 * 32];   // [row][k]
    __shared__ float ws[32 * 128];   // [k][col]

    const int dir = blockIdx.z;
    const float* W    = dir ? W1 : W0;
    const float* bias = dir ? bias1 : bias0;
    const size_t m0 = (size_t)blockIdx.y * 128;
    const int    c0 = blockIdx.x * 128;
    const int tid = threadIdx.x;
    const int tx = tid & 31;
    const int ty = tid >> 5;

    unsigned long long acc[16][2];
    #pragma unroll
    for (int i = 0; i < 16; ++i) { acc[i][0] = 0ull; acc[i][1] = 0ull; }

    for (int kc = 0; kc < 4; ++kc) {
        if (kc) __syncthreads();
        #pragma unroll
        for (int i = tid; i < 1024; i += 256) {
            int r = i >> 3, kq = i & 7;
            *(float4*)(xs + r * 32 + kq * 4) =
                *(const float4*)(x + (m0 + r) * 128 + kc * 32 + kq * 4);
        }
        #pragma unroll
        for (int i = tid; i < 1024; i += 256) {
            int k = i >> 5, c4 = (i & 31) * 4;
            *(float4*)(ws + k * 128 + c4) =
                *(const float4*)(W + (size_t)(kc * 32 + k) * 512 + c0 + c4);
        }
        __syncthreads();

        #pragma unroll
        for (int kq = 0; kq < 8; ++kq) {
            float4 av[16];
            #pragma unroll
            for (int i = 0; i < 16; ++i)
                av[i] = *(const float4*)(xs + (ty * 16 + i) * 32 + kq * 4);
            #pragma unroll
            for (int kk = 0; kk < 4; ++kk) {
                ulonglong2 bv = *(const ulonglong2*)(ws + (kq * 4 + kk) * 128 + tx * 4);
                #pragma unroll
                for (int i = 0; i < 16; ++i) {
                    float a = (kk == 0) ? av[i].x : (kk == 1) ? av[i].y
                            : (kk == 2) ? av[i].z : av[i].w;
                    unsigned long long ap = pk2(a, a);
                    acc[i][0] = ffma2(ap, bv.x, acc[i][0]);
                    acc[i][1] = ffma2(ap, bv.y, acc[i][1]);
                }
            }
        }
    }

    float bl0 = bias[c0 + tx * 4 + 0], bl1 = bias[c0 + tx * 4 + 1];
    float bl2 = bias[c0 + tx * 4 + 2], bl3 = bias[c0 + tx * 4 + 3];
    #pragma unroll
    for (int i = 0; i < 16; ++i) {
        float v0, v1, v2, v3;
        upk2(acc[i][0], v0, v1);
        upk2(acc[i][1], v2, v3);
        float4 o = make_float4(v0 + bl0, v1 + bl1, v2 + bl2, v3 + bl3);
        *(float4*)(g_zpre + ((size_t)dir * (BB * TT) + m0 + ty * 16 + i) * 512
                   + c0 + tx * 4) = o;
    }
}

// ---------------------------------------------------------------------------
// Phase 2: recurrence. 4-CTA clusters, 4 batch rows per cluster.
//   cid = blockIdx.x/4 (32 clusters): dir = cid/16, b0 = (cid%16)*4.
//   CTA rank owns cols {g*128 + rank*32 + uu}, uu in [0,32): 128 cols/CTA.
//   Each col handled by 2 threads (kh = tid>>7 splits K): w2[32] = 64 regs.
//   Partial z combined through zsh0/zsh1; gate threads (tid<128) do the
//   nonlinearity for one (row, unit) and broadcast h to all 4 CTAs (DSMEM).
//   R4-proven barrier placement: arrive+wait together at end of each step.
// ---------------------------------------------------------------------------
__global__ void __cluster_dims__(4, 1, 1) __launch_bounds__(256, 1)
lstm_rec(const float* __restrict__ Wfw, const float* __restrict__ Wbw,
         float* __restrict__ out) {
    __shared__ __align__(16) float hbuf[2][4][128];  // [parity][row][unit]
    __shared__ float zsh0[4][128];                   // kh=0 partial (+zpre)
    __shared__ float zsh1[4][128];                   // kh=1 partial

    uint32_t rank;
    asm("mov.u32 %0, %%cluster_ctarank;" : "=r"(rank));
    const int cid = blockIdx.x >> 2;
    const int dir = cid >> 4;
    const int b0  = (cid & 15) * 4;
    const int tid = threadIdx.x;
    const int kh  = tid >> 7;            // K half: warps 0-3 -> 0, 4-7 -> 1
    const int lc  = tid & 127;           // local col 0..127
    const int uu  = lc & 31;             // unit within CTA ownership
    const int col = (lc >> 5) * 128 + (int)rank * 32 + uu;  // global z col
    const int khalf = kh * 64;
    const float* W = dir ? Wbw : Wfw;

    // W_h half-column -> registers (rows 128+khalf .. 128+khalf+63 of W)
    unsigned long long w2[32];
    #pragma unroll
    for (int i = 0; i < 32; ++i) {
        int k = 128 + khalf + 2 * i;
        w2[i] = pk2(W[(size_t)k * 512 + col], W[(size_t)(k + 1) * 512 + col]);
    }

    for (int i = tid; i < 1024; i += 256) ((float*)hbuf)[i] = 0.0f;

    const uint32_t hb_l = (uint32_t)__cvta_generic_to_shared(&hbuf[0][0][0]);
    uint32_t rmA, rmB, rmC;
    asm("mapa.shared::cluster.u32 %0, %1, %2;" : "=r"(rmA) : "r"(hb_l), "r"(rank ^ 1u));
    asm("mapa.shared::cluster.u32 %0, %1, %2;" : "=r"(rmB) : "r"(hb_l), "r"(rank ^ 2u));
    asm("mapa.shared::cluster.u32 %0, %1, %2;" : "=r"(rmC) : "r"(hb_l), "r"(rank ^ 3u));

    // z_pre streaming (4 batch rows); only kh==0 threads consume z_pre
    const int tq0 = dir ? (TT - 1) : 0;
    const ptrdiff_t dstep = dir ? -512 : 512;
    const size_t rstride = (size_t)TT * 512;
    const float* zp = g_zpre + ((size_t)dir * (BB * TT) + (size_t)b0 * TT + tq0) * 512 + col;
    float zc0 = 0.f, zc1 = 0.f, zc2 = 0.f, zc3 = 0.f;
    if (kh == 0) {
        zc0 = __ldcs(zp);
        zc1 = __ldcs(zp + rstride);
        zc2 = __ldcs(zp + 2 * rstride);
        zc3 = __ldcs(zp + 3 * rstride);
    }

    float c_state = 0.0f;                 // valid on gate threads (tid<128)
    const int grow = tid >> 5;            // gate-thread batch row 0..3
    const int gun  = tid & 31;            // gate-thread unit (within CTA)
    const int myu  = (int)rank * 32;      // global unit base of this CTA

    __syncthreads();
    // hbuf init visible cluster-wide before any DSMEM stores
    asm volatile("barrier.cluster.arrive.aligned;" ::: "memory");
    asm volatile("barrier.cluster.wait.aligned;"   ::: "memory");

    for (int t = 0; t < TT; ++t) {
        const int p  = t & 1;
        const int pn = p ^ 1;

        float zn0 = 0.f, zn1 = 0.f, zn2 = 0.f, zn3 = 0.f;   // prefetch next z
        if (t + 1 < TT) {
            zp += dstep;
            if (kh == 0) {
                zn0 = __ldcs(zp);
                zn1 = __ldcs(zp + rstride);
                zn2 = __ldcs(zp + 2 * rstride);
                zn3 = __ldcs(zp + 3 * rstride);
            }
        }

        // z partial = h[khalf:khalf+64] @ W_h[khalf:.., col] for 4 rows
        unsigned long long a0 = 0ull, a1 = 0ull, a2 = 0ull, a3 = 0ull;
        #pragma unroll
        for (int j = 0; j < 16; ++j) {
            ulonglong2 h0 = *(const ulonglong2*)(&hbuf[p][0][khalf + j * 4]);
            ulonglong2 h1 = *(const ulonglong2*)(&hbuf[p][1][khalf + j * 4]);
            a0 = ffma2(h0.x, w2[2 * j],     a0);
            a0 = ffma2(h0.y, w2[2 * j + 1], a0);
            a1 = ffma2(h1.x, w2[2 * j],     a1);
            a1 = ffma2(h1.y, w2[2 * j + 1], a1);
            ulonglong2 h2 = *(const ulonglong2*)(&hbuf[p][2][khalf + j * 4]);
            ulonglong2 h3 = *(const ulonglong2*)(&hbuf[p][3][khalf + j * 4]);
            a2 = ffma2(h2.x, w2[2 * j],     a2);
            a2 = ffma2(h2.y, w2[2 * j + 1], a2);
            a3 = ffma2(h3.x, w2[2 * j],     a3);
            a3 = ffma2(h3.y, w2[2 * j + 1], a3);
        }
        float lo, hi;
        upk2(a0, lo, hi); float s0 = lo + hi;
        upk2(a1, lo, hi); float s1 = lo + hi;
        upk2(a2, lo, hi); float s2 = lo + hi;
        upk2(a3, lo, hi); float s3 = lo + hi;
        if (kh == 0) {
            zsh0[0][lc] = s0 + zc0;
            zsh0[1][lc] = s1 + zc1;
            zsh0[2][lc] = s2 + zc2;
            zsh0[3][lc] = s3 + zc3;
        } else {
            zsh1[0][lc] = s0;
            zsh1[1][lc] = s1;
            zsh1[2][lc] = s2;
            zsh1[3][lc] = s3;
        }
        zc0 = zn0; zc1 = zn1; zc2 = zn2; zc3 = zn3;
        __syncthreads();

        if (tid < 128) {                   // one thread per (row, unit)
            float zi = zsh0[grow][gun]      + zsh1[grow][gun];
            float zj = zsh0[grow][32 + gun] + zsh1[grow][32 + gun];
            float zf = zsh0[grow][64 + gun] + zsh1[grow][64 + gun];
            float zo = zsh0[grow][96 + gun] + zsh1[grow][96 + gun];
            c_state = c_state * sigm(zf + 1.0f) + sigm(zi) * tanh_f(zj);
            float hn = sigm(zo) * tanh_f(c_state);

            if (t < TT - 1) {
                hbuf[pn][grow][myu + gun] = hn;
                uint32_t off = (uint32_t)(((pn * 4 + grow) * 128 + myu + gun) * 4);
                asm volatile("st.shared::cluster.f32 [%0], %1;"
                             :: "r"(rmA + off), "f"(hn) : "memory");
                asm volatile("st.shared::cluster.f32 [%0], %1;"
                             :: "r"(rmB + off), "f"(hn) : "memory");
                asm volatile("st.shared::cluster.f32 [%0], %1;"
                             :: "r"(rmC + off), "f"(hn) : "memory");
            }

            const int tq = dir ? (TT - 1 - t) : t;
            out[((size_t)(b0 + grow) * TT + tq) * 256 + dir * 128 + myu + gun] = hn;
        }
        __syncthreads();                   // local h half visible CTA-wide

        // release our DSMEM stores / wait for all CTAs' step-t stores
        asm volatile("barrier.cluster.arrive.aligned;" ::: "memory");
        asm volatile("barrier.cluster.wait.aligned;"   ::: "memory");
    }
}

extern "C" void kernel_launch(void* const* d_in, const int* in_sizes, int n_in,
                              void* d_out, int out_size) {
    const float* x   = (const float*)d_in[0];
    const float* Wfw = (const float*)d_in[1];
    const float* bfw = (const float*)d_in[2];
    const float* Wbw = (const float*)d_in[3];
    const float* bbw = (const float*)d_in[4];
    float* out = (float*)d_out;

    dim3 g1(4, 1024, 2);
    lstm_pre<<<g1, 256>>>(x, Wfw, bfw, Wbw, bbw);
    lstm_rec<<<128, 256>>>(Wfw, Wbw, out);
}

// round 13
// speedup vs baseline: 1.5025x; 1.1987x over previous
#include <cuda_runtime.h>
#include <cstdint>
#include <cstddef>

#define TT 2048
#define BB 64

// 512 MB scratch: precomputed input projections [2][B*T][512]
__device__ float g_zpre[(size_t)2 * BB * TT * 512];

// ---------------- packed f32x2 helpers ----------------
__device__ __forceinline__ unsigned long long pk2(float lo, float hi) {
    unsigned long long r;
    asm("mov.b64 %0, {%1,%2};" : "=l"(r) : "f"(lo), "f"(hi));
    return r;
}
__device__ __forceinline__ void upk2(unsigned long long v, float& lo, float& hi) {
    asm("mov.b64 {%0,%1}, %2;" : "=f"(lo), "=f"(hi) : "l"(v));
}
__device__ __forceinline__ unsigned long long ffma2(unsigned long long a,
                                                    unsigned long long b,
                                                    unsigned long long c) {
    unsigned long long d;
    asm("fma.rn.f32x2 %0, %1, %2, %3;" : "=l"(d) : "l"(a), "l"(b), "l"(c));
    return d;
}
__device__ __forceinline__ float sigm(float x) {
    return __fdividef(1.0f, 1.0f + __expf(-x));
}
// branchless tanh: 1 - 2/(e^{2x}+1); exact limits, MUFU precision
__device__ __forceinline__ float tanh_f(float x) {
    float e = __expf(2.0f * x);
    return 1.0f - __fdividef(2.0f, e + 1.0f);
}

// ---------------------------------------------------------------------------
// Phase 1: Zpre = x @ W[0:128,:] + b.   (unchanged — proven)
// ---------------------------------------------------------------------------
__global__ void __launch_bounds__(256, 1)
lstm_pre(const float* __restrict__ x,
         const float* __restrict__ W0, const float* __restrict__ bias0,
         const float* __restrict__ W1, const float* __restrict__ bias1) {
    __shared__ float xs[128 * 32];   // [row][k]
    __shared__ float ws[32 * 128];   // [k][col]

    const int dir = blockIdx.z;
    const float* W    = dir ? W1 : W0;
    const float* bias = dir ? bias1 : bias0;
    const size_t m0 = (size_t)blockIdx.y * 128;
    const int    c0 = blockIdx.x * 128;
    const int tid = threadIdx.x;
    const int tx = tid & 31;
    const int ty = tid >> 5;

    unsigned long long acc[16][2];
    #pragma unroll
    for (int i = 0; i < 16; ++i) { acc[i][0] = 0ull; acc[i][1] = 0ull; }

    for (int kc = 0; kc < 4; ++kc) {
        if (kc) __syncthreads();
        #pragma unroll
        for (int i = tid; i < 1024; i += 256) {
            int r = i >> 3, kq = i & 7;
            *(float4*)(xs + r * 32 + kq * 4) =
                *(const float4*)(x + (m0 + r) * 128 + kc * 32 + kq * 4);
        }
        #pragma unroll
        for (int i = tid; i < 1024; i += 256) {
            int k = i >> 5, c4 = (i & 31) * 4;
            *(float4*)(ws + k * 128 + c4) =
                *(const float4*)(W + (size_t)(kc * 32 + k) * 512 + c0 + c4);
        }
        __syncthreads();

        #pragma unroll
        for (int kq = 0; kq < 8; ++kq) {
            float4 av[16];
            #pragma unroll
            for (int i = 0; i < 16; ++i)
                av[i] = *(const float4*)(xs + (ty * 16 + i) * 32 + kq * 4);
            #pragma unroll
            for (int kk = 0; kk < 4; ++kk) {
                ulonglong2 bv = *(const ulonglong2*)(ws + (kq * 4 + kk) * 128 + tx * 4);
                #pragma unroll
                for (int i = 0; i < 16; ++i) {
                    float a = (kk == 0) ? av[i].x : (kk == 1) ? av[i].y
                            : (kk == 2) ? av[i].z : av[i].w;
                    unsigned long long ap = pk2(a, a);
                    acc[i][0] = ffma2(ap, bv.x, acc[i][0]);
                    acc[i][1] = ffma2(ap, bv.y, acc[i][1]);
                }
            }
        }
    }

    float bl0 = bias[c0 + tx * 4 + 0], bl1 = bias[c0 + tx * 4 + 1];
    float bl2 = bias[c0 + tx * 4 + 2], bl3 = bias[c0 + tx * 4 + 3];
    #pragma unroll
    for (int i = 0; i < 16; ++i) {
        float v0, v1, v2, v3;
        upk2(acc[i][0], v0, v1);
        upk2(acc[i][1], v2, v3);
        float4 o = make_float4(v0 + bl0, v1 + bl1, v2 + bl2, v3 + bl3);
        *(float4*)(g_zpre + ((size_t)dir * (BB * TT) + m0 + ty * 16 + i) * 512
                   + c0 + tx * 4) = o;
    }
}

// ---------------------------------------------------------------------------
// Phase 2: recurrence. R4 structure EXACTLY (single full-K FMA loop, zbuf
// gates), with the per-step cluster barrier replaced by a monotonic-tag
// flag handshake:
//   - gate thread (grow,gu) stores h to peer hbuf (st.shared::cluster) then
//     publishes flags[grow*64+gu] = t+1 in peer smem with st.release.cluster
//   - before FMA of step t (t>0), every thread spins on its own smem flags
//     with ld.acquire until min(flags) >= t (each lane checks 4 of 128).
// Double-buffered hbuf keeps the +/-1 step skew race-free: the peer can only
// write buffer (t&1) after seeing our flag t+1, which we publish after our
// last read of that buffer.
// ---------------------------------------------------------------------------
__global__ void __cluster_dims__(2, 1, 1) __launch_bounds__(256, 1)
lstm_rec(const float* __restrict__ Wfw, const float* __restrict__ Wbw,
         float* __restrict__ out) {
    __shared__ __align__(16) float hbuf[2][2][128];  // [parity][row][unit]
    __shared__ float zbuf[2][256];                   // [row][local col]
    __shared__ __align__(16) uint32_t flags[128];    // peer-progress tags

    uint32_t rank;
    asm("mov.u32 %0, %%cluster_ctarank;" : "=r"(rank));
    const uint32_t peer = rank ^ 1u;
    const int cid = blockIdx.x >> 1;
    const int dir = cid >> 5;
    const int b0  = (cid & 31) * 2;
    const int tid = threadIdx.x;
    const int g   = tid >> 6;                        // gate 0..3 (i,j,f,o)
    const int ul  = tid & 63;                        // unit within half
    const int col = g * 128 + (int)rank * 64 + ul;   // owned z column
    const float* W = dir ? Wbw : Wfw;

    // W_h column -> registers, packed over k-pairs (rows 128..255 of W)
    unsigned long long w2[64];
    #pragma unroll
    for (int kp = 0; kp < 64; ++kp)
        w2[kp] = pk2(W[(size_t)(128 + 2 * kp) * 512 + col],
                     W[(size_t)(129 + 2 * kp) * 512 + col]);

    for (int i = tid; i < 512; i += 256) ((float*)hbuf)[i] = 0.0f;
    if (tid < 128) flags[tid] = 0u;

    const uint32_t hb_l = (uint32_t)__cvta_generic_to_shared(&hbuf[0][0][0]);
    const uint32_t fl_l = (uint32_t)__cvta_generic_to_shared(&flags[0]);
    uint32_t rm_hb, rm_fl;
    asm("mapa.shared::cluster.u32 %0, %1, %2;" : "=r"(rm_hb) : "r"(hb_l), "r"(peer));
    asm("mapa.shared::cluster.u32 %0, %1, %2;" : "=r"(rm_fl) : "r"(fl_l), "r"(peer));

    // z_pre streaming pointers (rows b0, b0+1)
    const int tq0 = dir ? (TT - 1) : 0;
    const ptrdiff_t dstep = dir ? -512 : 512;
    const float* zp0 = g_zpre + ((size_t)dir * (BB * TT) + (size_t)b0 * TT + tq0) * 512 + col;
    const float* zp1 = zp0 + (size_t)TT * 512;
    float zc0 = __ldcs(zp0), zc1 = __ldcs(zp1);

    float c_state = 0.0f;
    const int grow = (tid >> 6) & 1;   // gate-thread batch row (tid<128)
    const int gu   = tid & 63;         // gate-thread unit within owned half
    const int loc_u = (int)rank * 64;

    // per-thread poll slot: lane l watches flags[l*4 .. l*4+3]
    const uint32_t my_fl = fl_l + (uint32_t)((tid & 31) * 16);

    __syncthreads();
    // hbuf/flags init visible cluster-wide before any peer DSMEM stores
    asm volatile("barrier.cluster.arrive.aligned;" ::: "memory");
    asm volatile("barrier.cluster.wait.aligned;"   ::: "memory");

    for (int t = 0; t < TT; ++t) {
        const int p  = t & 1;
        const int pn = p ^ 1;

        float zn0 = 0.0f, zn1 = 0.0f;            // prefetch next step's z
        if (t + 1 < TT) {
            zp0 += dstep; zp1 += dstep;
            zn0 = __ldcs(zp0); zn1 = __ldcs(zp1);
        }

        // ---- wait for peer's h of step t-1 (tag >= t) ----
        if (t > 0) {
            const uint32_t need = (uint32_t)t;
            for (;;) {
                uint32_t v0, v1, v2, v3;
                asm volatile("ld.acquire.cluster.shared::cta.u32 %0, [%1];"
                             : "=r"(v0) : "r"(my_fl) : "memory");
                asm volatile("ld.acquire.cluster.shared::cta.u32 %0, [%1];"
                             : "=r"(v1) : "r"(my_fl + 4) : "memory");
                asm volatile("ld.acquire.cluster.shared::cta.u32 %0, [%1];"
                             : "=r"(v2) : "r"(my_fl + 8) : "memory");
                asm volatile("ld.acquire.cluster.shared::cta.u32 %0, [%1];"
                             : "=r"(v3) : "r"(my_fl + 12) : "memory");
                uint32_t mn = min(min(v0, v1), min(v2, v3));
                if (__all_sync(0xffffffffu, mn >= need)) break;
            }
        }

        // ---- z = h @ W_h[:,col]  (R4-exact loop; 2 accumulators) ----
        unsigned long long a0 = 0ull, a1 = 0ull;
        #pragma unroll
        for (int q = 0; q < 32; ++q) {
            ulonglong2 h0 = *(const ulonglong2*)(&hbuf[p][0][q * 4]);
            ulonglong2 h1 = *(const ulonglong2*)(&hbuf[p][1][q * 4]);
            a0 = ffma2(h0.x, w2[2 * q],     a0);
            a0 = ffma2(h0.y, w2[2 * q + 1], a0);
            a1 = ffma2(h1.x, w2[2 * q],     a1);
            a1 = ffma2(h1.y, w2[2 * q + 1], a1);
        }
        float s0l, s0h, s1l, s1h;
        upk2(a0, s0l, s0h);
        upk2(a1, s1l, s1h);
        zbuf[0][tid] = s0l + s0h + zc0;
        zbuf[1][tid] = s1l + s1h + zc1;
        zc0 = zn0; zc1 = zn1;
        __syncthreads();

        if (tid < 128) {                          // one thread per (row, unit)
            float zi = zbuf[grow][gu];
            float zj = zbuf[grow][64  + gu];
            float zf = zbuf[grow][128 + gu];
            float zo = zbuf[grow][192 + gu];
            c_state = c_state * sigm(zf + 1.0f) + sigm(zi) * tanh_f(zj);
            float hn = sigm(zo) * tanh_f(c_state);

            hbuf[pn][grow][loc_u + gu] = hn;      // local half for our next step
            if (t < TT - 1) {
                // push our half to peer, then publish progress tag (release
                // orders the h store before the flag becomes visible)
                uint32_t hoff = (uint32_t)(((pn * 2 + grow) * 128 + loc_u + gu) * 4);
                asm volatile("st.shared::cluster.f32 [%0], %1;"
                             :: "r"(rm_hb + hoff), "f"(hn) : "memory");
                uint32_t foff = (uint32_t)((grow * 64 + gu) * 4);
                asm volatile("st.release.cluster.shared::cluster.u32 [%0], %1;"
                             :: "r"(rm_fl + foff), "r"((uint32_t)(t + 1)) : "memory");
            }

            const int tq = dir ? (TT - 1 - t) : t;
            out[((size_t)(b0 + grow) * TT + tq) * 256 + dir * 128 + loc_u + gu] = hn;
        }
        __syncthreads();                          // local h half visible CTA-wide
    }
}

extern "C" void kernel_launch(void* const* d_in, const int* in_sizes, int n_in,
                              void* d_out, int out_size) {
    const float* x   = (const float*)d_in[0];
    const float* Wfw = (const float*)d_in[1];
    const float* bfw = (const float*)d_in[2];
    const float* Wbw = (const float*)d_in[3];
    const float* bbw = (const float*)d_in[4];
    float* out = (float*)d_out;

    dim3 g1(4, 1024, 2);
    lstm_pre<<<g1, 256>>>(x, Wfw, bfw, Wbw, bbw);
    lstm_rec<<<128, 256>>>(Wfw, Wbw, out);
}